// round 6
// baseline (speedup 1.0000x reference)
#include <cuda_runtime.h>
#include <math.h>

#define C_CLS 100
#define KP    8
#define D_DIM 512
#define LAMBDA 0.1f
#define WS 0.0625f
#define WO (0.5f/99.0f)
#define SQWS 0.25f
#define SQWO 0.07106690545187014f
#define SQWSWO 0.017766726362967535f
#define INV_SUB_T 20.0f
#define INV_PRIOR_T (1.0f/0.07f)
#define INV_ROUT_T (1.0f/0.07f)
#define NEPS 1e-8f
#define MSZ 107

__device__ __align__(16) float g_Bmat[900 * D_DIM];   // per class: 8 norm protos + 1 scaled W row
__device__ __align__(16) float g_centers[C_CLS * D_DIM];
__device__ __align__(16) float g_csum[D_DIM];
__device__ __align__(16) float g_bvec[C_CLS * D_DIM];
__device__ __align__(16) float g_rinv[32768];
__device__ float g_GCC[C_CLS * C_CLS];
__device__ float g_GPC[C_CLS * KP * C_CLS];
__device__ float g_GPP[C_CLS * KP * KP];
__device__ float g_CB[C_CLS * C_CLS];
__device__ float g_PB[C_CLS * KP];

__device__ __forceinline__ float warp_sum(float s) {
#pragma unroll
    for (int o = 16; o > 0; o >>= 1) s += __shfl_xor_sync(0xffffffffu, s, o);
    return s;
}

__device__ __forceinline__ float warp_dot512(const float* __restrict__ u,
                                             const float* __restrict__ v, int lane) {
    float s = 0.f;
#pragma unroll
    for (int i = 0; i < 4; i++) {
        float4 a = *reinterpret_cast<const float4*>(u + lane * 4 + i * 128);
        float4 b = *reinterpret_cast<const float4*>(v + lane * 4 + i * 128);
        s += a.x * b.x + a.y * b.y + a.z * b.z + a.w * b.w;
    }
    return warp_sum(s);
}

// -------- 1/||h_row|| --------
__global__ void k_rnorm(const float* __restrict__ h) {
    int row = blockIdx.x * 8 + (threadIdx.x >> 5);
    int lane = threadIdx.x & 31;
    const float* r = h + (size_t)row * D_DIM + lane * 4;
    float s = 0.f;
#pragma unroll
    for (int i = 0; i < 4; i++) {
        float4 a = *reinterpret_cast<const float4*>(r + i * 128);
        s += a.x * a.x + a.y * a.y + a.z * a.z + a.w * a.w;
    }
    s = warp_sum(s);
    if (lane == 0) g_rinv[row] = 1.0f / fmaxf(sqrtf(s), NEPS);
}

// -------- normalize prototypes into g_Bmat rows 0..7 per class --------
__global__ void k_pnorm(const float* __restrict__ P) {
    int c = blockIdx.x, w = threadIdx.x >> 5, lane = threadIdx.x & 31;
    const float* src = P + ((size_t)c * KP + w) * D_DIM + lane * 4;
    float4 a[4]; float s = 0.f;
#pragma unroll
    for (int i = 0; i < 4; i++) {
        a[i] = *reinterpret_cast<const float4*>(src + i * 128);
        s += a[i].x*a[i].x + a[i].y*a[i].y + a[i].z*a[i].z + a[i].w*a[i].w;
    }
    s = warp_sum(s);
    float inv = 1.0f / fmaxf(sqrtf(s), NEPS);
    float* dst = g_Bmat + ((size_t)c * 9 + w) * D_DIM + lane * 4;
#pragma unroll
    for (int i = 0; i < 4; i++) {
        float4 o; o.x=a[i].x*inv; o.y=a[i].y*inv; o.z=a[i].z*inv; o.w=a[i].w*inv;
        *reinterpret_cast<float4*>(dst + i * 128) = o;
    }
}

// -------- centers = l2norm(mean_k Pn) --------
__global__ void k_centers() {
    int c = blockIdx.x, tid = threadIdx.x;
    __shared__ float red[256];
    __shared__ float sm[D_DIM];
    float acc = 0.f;
    for (int d = tid; d < D_DIM; d += 256) {
        float m = 0.f;
#pragma unroll
        for (int k = 0; k < KP; k++) m += g_Bmat[((size_t)c * 9 + k) * D_DIM + d];
        m *= 0.125f;
        sm[d] = m; acc += m * m;
    }
    red[tid] = acc; __syncthreads();
    for (int s = 128; s > 0; s >>= 1) { if (tid < s) red[tid] += red[tid + s]; __syncthreads(); }
    float inv = 1.0f / fmaxf(sqrtf(red[0]), NEPS);
    for (int d = tid; d < D_DIM; d += 256) g_centers[(size_t)c * D_DIM + d] = sm[d] * inv;
}

__global__ void k_csum() {
    int d = threadIdx.x;
    float s = 0.f;
    for (int c = 0; c < C_CLS; c++) s += g_centers[(size_t)c * D_DIM + d];
    g_csum[d] = s;
}

__global__ void k_bvec() {
    int c = blockIdx.x, tid = threadIdx.x;
    for (int d = tid; d < D_DIM; d += 256) {
        float sp = 0.f;
#pragma unroll
        for (int k = 0; k < KP; k++) sp += g_Bmat[((size_t)c * 9 + k) * D_DIM + d];
        g_bvec[(size_t)c * D_DIM + d] =
            WS * sp - WO * (g_csum[d] - g_centers[(size_t)c * D_DIM + d]);
    }
}

// -------- shared Grams --------
__global__ void k_gcc() {
    int a = blockIdx.x, w = threadIdx.x >> 5, lane = threadIdx.x & 31;
    const float* ca = g_centers + (size_t)a * D_DIM;
    for (int b = w; b < C_CLS; b += 8) {
        float s = warp_dot512(ca, g_centers + (size_t)b * D_DIM, lane);
        if (lane == 0) g_GCC[a * C_CLS + b] = s;
    }
}
__global__ void k_gpc() {
    int pr = blockIdx.x;
    int w = threadIdx.x >> 5, lane = threadIdx.x & 31;
    const float* prow = g_Bmat + ((size_t)(pr >> 3) * 9 + (pr & 7)) * D_DIM;
    for (int j = w; j < C_CLS; j += 8) {
        float s = warp_dot512(prow, g_centers + (size_t)j * D_DIM, lane);
        if (lane == 0) g_GPC[pr * C_CLS + j] = s;
    }
}
__global__ void k_gpp() {
    int c = blockIdx.x, w = threadIdx.x >> 5, lane = threadIdx.x & 31;
    for (int e = w; e < 64; e += 8) {
        float s = warp_dot512(g_Bmat + ((size_t)c * 9 + (e >> 3)) * D_DIM,
                              g_Bmat + ((size_t)c * 9 + (e & 7)) * D_DIM, lane);
        if (lane == 0) g_GPP[c * 64 + e] = s;
    }
}
__global__ void k_cbpb() {
    int c = blockIdx.x, w = threadIdx.x >> 5, lane = threadIdx.x & 31;
    const float* bv = g_bvec + (size_t)c * D_DIM;
    for (int idx = w; idx < 108; idx += 8) {
        float s;
        if (idx < C_CLS) {
            s = warp_dot512(g_centers + (size_t)idx * D_DIM, bv, lane);
            if (lane == 0) g_CB[c * C_CLS + idx] = s;
        } else {
            s = warp_dot512(g_Bmat + ((size_t)c * 9 + (idx - 100)) * D_DIM, bv, lane);
            if (lane == 0) g_PB[c * KP + (idx - 100)] = s;
        }
    }
}

// -------- Woodbury solve per class: W row -> g_Bmat[c*9+8] --------
__global__ __launch_bounds__(256) void k_solve() {
    int c = blockIdx.x, tid = threadIdx.x;
    __shared__ float M[MSZ * MSZ];
    __shared__ float v[MSZ];
    for (int idx = tid; idx < MSZ * MSZ; idx += 256) {
        int i = idx / MSZ, j = idx % MSZ;
        if (j > i) continue;
        float val;
        if (i < 8) {
            val = WS * g_GPP[c * 64 + i * 8 + j];
        } else {
            int ci = (i - 8) + ((i - 8) >= c ? 1 : 0);
            if (j < 8) val = SQWSWO * g_GPC[(c * 8 + j) * C_CLS + ci];
            else {
                int cj = (j - 8) + ((j - 8) >= c ? 1 : 0);
                val = WO * g_GCC[ci * C_CLS + cj];
            }
        }
        if (i == j) val += LAMBDA;
        M[i * MSZ + j] = val;
    }
    if (tid < MSZ) {
        if (tid < 8) v[tid] = SQWS * g_PB[c * KP + tid];
        else {
            int ci = (tid - 8) + ((tid - 8) >= c ? 1 : 0);
            v[tid] = SQWO * g_CB[c * C_CLS + ci];
        }
    }
    __syncthreads();
    // Cholesky (lower)
    for (int k = 0; k < MSZ; k++) {
        if (tid == 0) M[k * MSZ + k] = sqrtf(M[k * MSZ + k]);
        __syncthreads();
        float dk = M[k * MSZ + k];
        for (int i = k + 1 + tid; i < MSZ; i += 256) M[i * MSZ + k] /= dk;
        __syncthreads();
        for (int j = k + 1; j < MSZ; j++) {
            float ljk = M[j * MSZ + k];
            for (int i = j + tid; i < MSZ; i += 256) M[i * MSZ + j] -= M[i * MSZ + k] * ljk;
        }
        __syncthreads();
    }
    // forward: L x = v
    for (int k = 0; k < MSZ; k++) {
        if (tid == 0) v[k] /= M[k * MSZ + k];
        __syncthreads();
        float vk = v[k];
        for (int i = k + 1 + tid; i < MSZ; i += 256) v[i] -= M[i * MSZ + k] * vk;
        __syncthreads();
    }
    // backward: L^T y = x
    for (int k = MSZ - 1; k >= 0; k--) {
        if (tid == 0) v[k] /= M[k * MSZ + k];
        __syncthreads();
        float vk = v[k];
        for (int i = tid; i < k; i += 256) v[i] -= M[k * MSZ + i] * vk;
        __syncthreads();
    }
    // W = (b - V^T y)/lambda, scaled by 1/ROUTING_T
    for (int d = tid; d < D_DIM; d += 256) {
        float acc = g_bvec[(size_t)c * D_DIM + d];
#pragma unroll
        for (int i = 0; i < 8; i++)
            acc -= SQWS * g_Bmat[((size_t)c * 9 + i) * D_DIM + d] * v[i];
        for (int j = 0; j < C_CLS; j++) {
            if (j == c) continue;
            int i = 8 + j - (j > c ? 1 : 0);
            acc -= SQWO * g_centers[(size_t)j * D_DIM + d] * v[i];
        }
        g_Bmat[((size_t)c * 9 + 8) * D_DIM + d] = acc * (1.0f / LAMBDA) * INV_ROUT_T;
    }
}

// -------- fused GEMM + softmax-pool epilogue --------
#define MT 512
#define CPB 4
#define KC 16
__global__ __launch_bounds__(256, 2) void k_gemm(const float* __restrict__ h,
                                                 float* __restrict__ out) {
    __shared__ float sh_h[KC * MT];        // k-major: [kk][local_row]
    __shared__ float sh_B[KC * CPB * 12];  // [kk][cls_local*12 + j]
    int t = threadIdx.x;
    int row0 = blockIdx.x * MT;
    int cls0 = blockIdx.y * CPB;
    int cl = t >> 6, m = t & 63;           // warp-uniform class
    float acc[8][9];
#pragma unroll
    for (int r = 0; r < 8; r++)
#pragma unroll
        for (int j = 0; j < 9; j++) acc[r][j] = 0.f;

    for (int k0 = 0; k0 < D_DIM; k0 += KC) {
        // load h tile (rows t and t+256), transpose into k-major smem
#pragma unroll
        for (int r2 = 0; r2 < 2; r2++) {
            int lr = t + 256 * r2;
            const float4* hp = reinterpret_cast<const float4*>(
                h + (size_t)(row0 + lr) * D_DIM + k0);
#pragma unroll
            for (int q = 0; q < 4; q++) {
                float4 a = hp[q];
                sh_h[(q * 4 + 0) * MT + lr] = a.x;
                sh_h[(q * 4 + 1) * MT + lr] = a.y;
                sh_h[(q * 4 + 2) * MT + lr] = a.z;
                sh_h[(q * 4 + 3) * MT + lr] = a.w;
            }
        }
        // load B tile: 36 rows x 16 k
        if (t < 144) {
            int jj = t >> 2, kq = (t & 3) * 4;
            int cc = jj / 9, j = jj % 9;
            const float4 a = *reinterpret_cast<const float4*>(
                g_Bmat + ((size_t)(cls0 + cc) * 9 + j) * D_DIM + k0 + kq);
            sh_B[(kq + 0) * 48 + cc * 12 + j] = a.x;
            sh_B[(kq + 1) * 48 + cc * 12 + j] = a.y;
            sh_B[(kq + 2) * 48 + cc * 12 + j] = a.z;
            sh_B[(kq + 3) * 48 + cc * 12 + j] = a.w;
        }
        __syncthreads();
#pragma unroll 4
        for (int kk = 0; kk < KC; kk++) {
            const float4* h4 = reinterpret_cast<const float4*>(sh_h + kk * MT + m * 8);
            float4 a0 = h4[0], a1 = h4[1];
            const float* bp = sh_B + kk * 48 + cl * 12;
            float4 b0 = *reinterpret_cast<const float4*>(bp);
            float4 b1 = *reinterpret_cast<const float4*>(bp + 4);
            float b8 = bp[8];
            float av[8] = {a0.x, a0.y, a0.z, a0.w, a1.x, a1.y, a1.z, a1.w};
            float bv[9] = {b0.x, b0.y, b0.z, b0.w, b1.x, b1.y, b1.z, b1.w, b8};
#pragma unroll
            for (int r = 0; r < 8; r++)
#pragma unroll
                for (int j = 0; j < 9; j++) acc[r][j] = fmaf(av[r], bv[j], acc[r][j]);
        }
        __syncthreads();
    }
    // epilogue: softmax-pool over 8 protos + residual
    int cls = cls0 + cl;
#pragma unroll
    for (int r = 0; r < 8; r++) {
        int row = row0 + m * 8 + r;
        float ri = g_rinv[row];
        float cs[8], mx = -1e30f;
#pragma unroll
        for (int j = 0; j < 8; j++) { cs[j] = acc[r][j] * ri; mx = fmaxf(mx, cs[j]); }
        float den = 0.f, num = 0.f;
#pragma unroll
        for (int j = 0; j < 8; j++) {
            float e = __expf((cs[j] - mx) * INV_SUB_T);
            den += e; num += e * cs[j];
        }
        float sim = num / den;
        out[(size_t)row * C_CLS + cls] = sim * INV_PRIOR_T + acc[r][8] * ri;
    }
}

extern "C" void kernel_launch(void* const* d_in, const int* in_sizes, int n_in,
                              void* d_out, int out_size) {
    const float* h = (const float*)d_in[0];
    const float* P = (const float*)d_in[1];
    float* out = (float*)d_out;
    (void)in_sizes; (void)n_in; (void)out_size;

    k_pnorm<<<100, 256>>>(P);
    k_rnorm<<<4096, 256>>>(h);
    k_centers<<<100, 256>>>();
    k_csum<<<1, 512>>>();
    k_bvec<<<100, 256>>>();
    k_gcc<<<100, 256>>>();
    k_gpc<<<800, 256>>>();
    k_gpp<<<100, 256>>>();
    k_cbpb<<<100, 256>>>();
    k_solve<<<100, 256>>>();
    k_gemm<<<dim3(64, 25), 256>>>(h, out);
}